// round 4
// baseline (speedup 1.0000x reference)
#include <cuda_runtime.h>

#define B_ 2
#define L_ 2048
#define E_ 1024
#define H_ 16
#define D_ 64

// Scratch (allocation-free rule: __device__ globals)
__device__ float g_Q[(size_t)B_ * L_ * E_];
__device__ float g_K[(size_t)B_ * L_ * E_];
__device__ float g_V[(size_t)B_ * L_ * E_];
__device__ float g_A[(size_t)B_ * L_ * E_];

// ---------------------------------------------------------------------------
// Kernel 1: fused per-head projections.  out[b,l,h,e] = sum_d X[b,l,h,d]*W[e,d]
// One block = 64 tokens x one head x one tensor {Q,K,V}. 256 threads, 4x4 tiles.
// ---------------------------------------------------------------------------
__global__ __launch_bounds__(256) void proj_kernel(
    const float* __restrict__ q_in, const float* __restrict__ k_in,
    const float* __restrict__ v_in, const float* __restrict__ Wq,
    const float* __restrict__ Wk, const float* __restrict__ Wv)
{
    __shared__ float Xt[64 * 64];  // [d][l]
    __shared__ float Wt[64 * 64];  // [d][e]

    const int tid = threadIdx.x;
    const int l0  = blockIdx.x * 64;
    const int h   = blockIdx.y;
    const int zz  = blockIdx.z;
    const int t   = zz / B_;
    const int b   = zz % B_;

    const float* X; const float* W; float* O;
    if (t == 0)      { X = q_in; W = Wq; O = g_Q; }
    else if (t == 1) { X = k_in; W = Wk; O = g_K; }
    else             { X = v_in; W = Wv; O = g_V; }

    // Load W transposed: Wt[d][e] = W[e][d]
    #pragma unroll
    for (int i = 0; i < 16; i++) {
        int idx = tid + i * 256;           // 0..4095
        int e = idx >> 6, d = idx & 63;
        Wt[d * 64 + e] = W[idx];
    }
    // Load X tile transposed: Xt[d][l]
    #pragma unroll
    for (int i = 0; i < 4; i++) {
        int idx = tid + i * 256;           // float4 index 0..1023
        int l = idx >> 4, d4 = (idx & 15) * 4;
        float4 v = *(const float4*)&X[((size_t)(b * L_ + l0 + l)) * E_ + h * 64 + d4];
        Xt[(d4 + 0) * 64 + l] = v.x;
        Xt[(d4 + 1) * 64 + l] = v.y;
        Xt[(d4 + 2) * 64 + l] = v.z;
        Xt[(d4 + 3) * 64 + l] = v.w;
    }
    __syncthreads();

    const int ty = tid >> 4, tx = tid & 15;
    const int r0 = ty * 4, c0 = tx * 4;
    float acc[4][4] = {};

    #pragma unroll 8
    for (int d = 0; d < 64; d++) {
        float4 a = *(const float4*)&Xt[d * 64 + r0];
        float4 w = *(const float4*)&Wt[d * 64 + c0];
        acc[0][0] += a.x * w.x; acc[0][1] += a.x * w.y; acc[0][2] += a.x * w.z; acc[0][3] += a.x * w.w;
        acc[1][0] += a.y * w.x; acc[1][1] += a.y * w.y; acc[1][2] += a.y * w.z; acc[1][3] += a.y * w.w;
        acc[2][0] += a.z * w.x; acc[2][1] += a.z * w.y; acc[2][2] += a.z * w.z; acc[2][3] += a.z * w.w;
        acc[3][0] += a.w * w.x; acc[3][1] += a.w * w.y; acc[3][2] += a.w * w.z; acc[3][3] += a.w * w.w;
    }

    #pragma unroll
    for (int i = 0; i < 4; i++) {
        float4 o = make_float4(acc[i][0], acc[i][1], acc[i][2], acc[i][3]);
        *(float4*)&O[((size_t)(b * L_ + l0 + r0 + i)) * E_ + h * 64 + c0] = o;
    }
}

// ---------------------------------------------------------------------------
// Kernel 2: flash-attention (streaming softmax), fp32.
// One block = 64 q-rows of one (b,h). K tiles of 64. 256 threads, 4x4 tiles.
// mask applied BEFORE 1/sqrt(E) scaling, per reference.
// ---------------------------------------------------------------------------
__global__ __launch_bounds__(256) void attn_kernel(const int* __restrict__ mask)
{
    __shared__ float Qt[64 * 64];   // [d][q]
    __shared__ float KPt[64 * 64];  // K tile [d][k], reused as P^T [k][q]
    __shared__ float Vs[64 * 64];   // V tile [k][d]

    const int tid = threadIdx.x;
    const int q0  = blockIdx.x * 64;
    const int h   = blockIdx.y;
    const int b   = blockIdx.z;
    const int ty  = tid >> 4, tx = tid & 15;
    const int r0  = ty * 4, c0 = tx * 4;

    // Load Q tile transposed
    #pragma unroll
    for (int i = 0; i < 4; i++) {
        int idx = tid + i * 256;
        int q = idx >> 4, d4 = (idx & 15) * 4;
        float4 v = *(const float4*)&g_Q[((size_t)(b * L_ + q0 + q)) * E_ + h * 64 + d4];
        Qt[(d4 + 0) * 64 + q] = v.x;
        Qt[(d4 + 1) * 64 + q] = v.y;
        Qt[(d4 + 2) * 64 + q] = v.z;
        Qt[(d4 + 3) * 64 + q] = v.w;
    }

    float m[4], lsum[4], o[4][4];
    #pragma unroll
    for (int i = 0; i < 4; i++) {
        m[i] = -1e30f; lsum[i] = 0.f;
        o[i][0] = o[i][1] = o[i][2] = o[i][3] = 0.f;
    }
    const float INV = 0.03125f;  // 1/sqrt(1024) exactly

    for (int k0 = 0; k0 < L_; k0 += 64) {
        // Load K (transposed) and V (row-major) tiles
        #pragma unroll
        for (int i = 0; i < 4; i++) {
            int idx = tid + i * 256;
            int k = idx >> 4, d4 = (idx & 15) * 4;
            size_t base = ((size_t)(b * L_ + k0 + k)) * E_ + h * 64 + d4;
            float4 kv = *(const float4*)&g_K[base];
            KPt[(d4 + 0) * 64 + k] = kv.x;
            KPt[(d4 + 1) * 64 + k] = kv.y;
            KPt[(d4 + 2) * 64 + k] = kv.z;
            KPt[(d4 + 3) * 64 + k] = kv.w;
            *(float4*)&Vs[k * 64 + d4] = *(const float4*)&g_V[base];
        }
        __syncthreads();

        // S = Q K^T (64x64x64)
        float s[4][4] = {};
        #pragma unroll 8
        for (int d = 0; d < 64; d++) {
            float4 a  = *(const float4*)&Qt[d * 64 + r0];
            float4 bb = *(const float4*)&KPt[d * 64 + c0];
            s[0][0] += a.x * bb.x; s[0][1] += a.x * bb.y; s[0][2] += a.x * bb.z; s[0][3] += a.x * bb.w;
            s[1][0] += a.y * bb.x; s[1][1] += a.y * bb.y; s[1][2] += a.y * bb.z; s[1][3] += a.y * bb.w;
            s[2][0] += a.z * bb.x; s[2][1] += a.z * bb.y; s[2][2] += a.z * bb.z; s[2][3] += a.z * bb.w;
            s[3][0] += a.w * bb.x; s[3][1] += a.w * bb.y; s[3][2] += a.w * bb.z; s[3][3] += a.w * bb.w;
        }

        // mask (before scale) + scale; -1e20/32 = -3.125e18
        #pragma unroll
        for (int i = 0; i < 4; i++) {
            const int4 mv = *(const int4*)&mask[((size_t)b * L_ + q0 + r0 + i) * L_ + k0 + c0];
            s[i][0] = mv.x ? s[i][0] * INV : -3.125e18f;
            s[i][1] = mv.y ? s[i][1] * INV : -3.125e18f;
            s[i][2] = mv.z ? s[i][2] * INV : -3.125e18f;
            s[i][3] = mv.w ? s[i][3] * INV : -3.125e18f;
        }

        // online softmax per q-row (row group = 16 consecutive lanes)
        #pragma unroll
        for (int i = 0; i < 4; i++) {
            float mt = fmaxf(fmaxf(s[i][0], s[i][1]), fmaxf(s[i][2], s[i][3]));
            #pragma unroll
            for (int off = 1; off < 16; off <<= 1)
                mt = fmaxf(mt, __shfl_xor_sync(0xffffffffu, mt, off));
            float mn = fmaxf(m[i], mt);
            float p0 = __expf(s[i][0] - mn);
            float p1 = __expf(s[i][1] - mn);
            float p2 = __expf(s[i][2] - mn);
            float p3 = __expf(s[i][3] - mn);
            float rs = p0 + p1 + p2 + p3;
            #pragma unroll
            for (int off = 1; off < 16; off <<= 1)
                rs += __shfl_xor_sync(0xffffffffu, rs, off);
            float fac = __expf(m[i] - mn);
            lsum[i] = lsum[i] * fac + rs;
            m[i] = mn;
            o[i][0] *= fac; o[i][1] *= fac; o[i][2] *= fac; o[i][3] *= fac;
            s[i][0] = p0; s[i][1] = p1; s[i][2] = p2; s[i][3] = p3;
        }
        __syncthreads();   // all threads done reading K tile

        // write P^T into KPt: Pt[k][q]
        #pragma unroll
        for (int j = 0; j < 4; j++) {
            float4 pv = make_float4(s[0][j], s[1][j], s[2][j], s[3][j]);
            *(float4*)&KPt[(c0 + j) * 64 + r0] = pv;
        }
        __syncthreads();

        // O += P V (64x64x64)
        #pragma unroll 8
        for (int k = 0; k < 64; k++) {
            float4 a  = *(const float4*)&KPt[k * 64 + r0];
            float4 bb = *(const float4*)&Vs[k * 64 + c0];
            o[0][0] += a.x * bb.x; o[0][1] += a.x * bb.y; o[0][2] += a.x * bb.z; o[0][3] += a.x * bb.w;
            o[1][0] += a.y * bb.x; o[1][1] += a.y * bb.y; o[1][2] += a.y * bb.z; o[1][3] += a.y * bb.w;
            o[2][0] += a.z * bb.x; o[2][1] += a.z * bb.y; o[2][2] += a.z * bb.z; o[2][3] += a.z * bb.w;
            o[3][0] += a.w * bb.x; o[3][1] += a.w * bb.y; o[3][2] += a.w * bb.z; o[3][3] += a.w * bb.w;
        }
        __syncthreads();   // before next tile load overwrites KPt/Vs
    }

    #pragma unroll
    for (int i = 0; i < 4; i++) {
        float inv = 1.0f / lsum[i];
        float4 ov = make_float4(o[i][0] * inv, o[i][1] * inv, o[i][2] * inv, o[i][3] * inv);
        *(float4*)&g_A[((size_t)(b * L_ + q0 + r0 + i)) * E_ + h * 64 + c0] = ov;
    }
}

// ---------------------------------------------------------------------------
// Kernel 3: FC epilogue. out[n,e] = sum_f A[n,f]*Wfc[e,f] + bfc[e]
// 64x64 output tiles, K-loop over 1024 in steps of 64.
// ---------------------------------------------------------------------------
__global__ __launch_bounds__(256) void fc_kernel(
    const float* __restrict__ Wfc, const float* __restrict__ bfc,
    float* __restrict__ out)
{
    __shared__ float At[64 * 64];  // [f][n]
    __shared__ float Wt[64 * 64];  // [f][e]

    const int tid = threadIdx.x;
    const int n0 = blockIdx.x * 64;
    const int e0 = blockIdx.y * 64;
    const int ty = tid >> 4, tx = tid & 15;
    const int r0 = ty * 4, c0 = tx * 4;

    float acc[4][4] = {};

    for (int f0 = 0; f0 < E_; f0 += 64) {
        #pragma unroll
        for (int i = 0; i < 4; i++) {
            int idx = tid + i * 256;
            int r = idx >> 4, f4 = (idx & 15) * 4;
            float4 av = *(const float4*)&g_A[(size_t)(n0 + r) * E_ + f0 + f4];
            At[(f4 + 0) * 64 + r] = av.x;
            At[(f4 + 1) * 64 + r] = av.y;
            At[(f4 + 2) * 64 + r] = av.z;
            At[(f4 + 3) * 64 + r] = av.w;
            float4 wv = *(const float4*)&Wfc[(size_t)(e0 + r) * E_ + f0 + f4];
            Wt[(f4 + 0) * 64 + r] = wv.x;
            Wt[(f4 + 1) * 64 + r] = wv.y;
            Wt[(f4 + 2) * 64 + r] = wv.z;
            Wt[(f4 + 3) * 64 + r] = wv.w;
        }
        __syncthreads();

        #pragma unroll 8
        for (int f = 0; f < 64; f++) {
            float4 a = *(const float4*)&At[f * 64 + r0];
            float4 w = *(const float4*)&Wt[f * 64 + c0];
            acc[0][0] += a.x * w.x; acc[0][1] += a.x * w.y; acc[0][2] += a.x * w.z; acc[0][3] += a.x * w.w;
            acc[1][0] += a.y * w.x; acc[1][1] += a.y * w.y; acc[1][2] += a.y * w.z; acc[1][3] += a.y * w.w;
            acc[2][0] += a.z * w.x; acc[2][1] += a.z * w.y; acc[2][2] += a.z * w.z; acc[2][3] += a.z * w.w;
            acc[3][0] += a.w * w.x; acc[3][1] += a.w * w.y; acc[3][2] += a.w * w.z; acc[3][3] += a.w * w.w;
        }
        __syncthreads();
    }

    const float4 bias = *(const float4*)&bfc[e0 + c0];
    #pragma unroll
    for (int i = 0; i < 4; i++) {
        float4 ov = make_float4(acc[i][0] + bias.x, acc[i][1] + bias.y,
                                acc[i][2] + bias.z, acc[i][3] + bias.w);
        *(float4*)&out[(size_t)(n0 + r0 + i) * E_ + e0 + c0] = ov;
    }
}

// ---------------------------------------------------------------------------
// Launch.  Input order (metadata): query, value, key, mask, Wq, Wk, Wv, Wfc, bfc
// ---------------------------------------------------------------------------
extern "C" void kernel_launch(void* const* d_in, const int* in_sizes, int n_in,
                              void* d_out, int out_size)
{
    const float* query = (const float*)d_in[0];
    const float* value = (const float*)d_in[1];
    const float* key   = (const float*)d_in[2];
    const int*   mask  = (const int*)d_in[3];
    const float* Wq    = (const float*)d_in[4];
    const float* Wk    = (const float*)d_in[5];
    const float* Wv    = (const float*)d_in[6];
    const float* Wfc   = (const float*)d_in[7];
    const float* bfc   = (const float*)d_in[8];
    float* out = (float*)d_out;

    proj_kernel<<<dim3(L_ / 64, H_, 3 * B_), 256>>>(query, key, value, Wq, Wk, Wv);
    attn_kernel<<<dim3(L_ / 64, H_, B_), 256>>>(mask);
    fc_kernel<<<dim3((B_ * L_) / 64, E_ / 64), 256>>>(Wfc, bfc, out);
}

// round 6
// speedup vs baseline: 1.0007x; 1.0007x over previous
#include <cuda_runtime.h>

#define B_ 2
#define L_ 2048
#define E_ 1024
#define H_ 16
#define D_ 64

// Scratch (allocation-free rule: __device__ globals)
__device__ float g_Q[(size_t)B_ * L_ * E_];
__device__ float g_K[(size_t)B_ * L_ * E_];
__device__ float g_V[(size_t)B_ * L_ * E_];
__device__ float g_A[(size_t)B_ * L_ * E_];

// ---------------------------------------------------------------------------
// Kernel 1: fused per-head projections.  out[b,l,h,e] = sum_d X[b,l,h,d]*W[e,d]
// One block = 64 tokens x one head x one tensor {Q,K,V}. 256 threads, 4x4 tiles.
// ---------------------------------------------------------------------------
__global__ __launch_bounds__(256) void proj_kernel(
    const float* __restrict__ q_in, const float* __restrict__ k_in,
    const float* __restrict__ v_in, const float* __restrict__ Wq,
    const float* __restrict__ Wk, const float* __restrict__ Wv)
{
    __shared__ float Xt[64 * 64];  // [d][l]
    __shared__ float Wt[64 * 64];  // [d][e]

    const int tid = threadIdx.x;
    const int l0  = blockIdx.x * 64;
    const int h   = blockIdx.y;
    const int zz  = blockIdx.z;
    const int t   = zz / B_;
    const int b   = zz % B_;

    const float* X; const float* W; float* O;
    if (t == 0)      { X = q_in; W = Wq; O = g_Q; }
    else if (t == 1) { X = k_in; W = Wk; O = g_K; }
    else             { X = v_in; W = Wv; O = g_V; }

    // Load W transposed: Wt[d][e] = W[e][d]
    #pragma unroll
    for (int i = 0; i < 16; i++) {
        int idx = tid + i * 256;           // 0..4095
        int e = idx >> 6, d = idx & 63;
        Wt[d * 64 + e] = W[idx];
    }
    // Load X tile transposed: Xt[d][l]
    #pragma unroll
    for (int i = 0; i < 4; i++) {
        int idx = tid + i * 256;           // float4 index 0..1023
        int l = idx >> 4, d4 = (idx & 15) * 4;
        float4 v = *(const float4*)&X[((size_t)(b * L_ + l0 + l)) * E_ + h * 64 + d4];
        Xt[(d4 + 0) * 64 + l] = v.x;
        Xt[(d4 + 1) * 64 + l] = v.y;
        Xt[(d4 + 2) * 64 + l] = v.z;
        Xt[(d4 + 3) * 64 + l] = v.w;
    }
    __syncthreads();

    const int ty = tid >> 4, tx = tid & 15;
    const int r0 = ty * 4, c0 = tx * 4;
    float acc[4][4] = {};

    #pragma unroll 8
    for (int d = 0; d < 64; d++) {
        float4 a = *(const float4*)&Xt[d * 64 + r0];
        float4 w = *(const float4*)&Wt[d * 64 + c0];
        acc[0][0] += a.x * w.x; acc[0][1] += a.x * w.y; acc[0][2] += a.x * w.z; acc[0][3] += a.x * w.w;
        acc[1][0] += a.y * w.x; acc[1][1] += a.y * w.y; acc[1][2] += a.y * w.z; acc[1][3] += a.y * w.w;
        acc[2][0] += a.z * w.x; acc[2][1] += a.z * w.y; acc[2][2] += a.z * w.z; acc[2][3] += a.z * w.w;
        acc[3][0] += a.w * w.x; acc[3][1] += a.w * w.y; acc[3][2] += a.w * w.z; acc[3][3] += a.w * w.w;
    }

    #pragma unroll
    for (int i = 0; i < 4; i++) {
        float4 o = make_float4(acc[i][0], acc[i][1], acc[i][2], acc[i][3]);
        *(float4*)&O[((size_t)(b * L_ + l0 + r0 + i)) * E_ + h * 64 + c0] = o;
    }
}

// ---------------------------------------------------------------------------
// Kernel 2: flash-attention (streaming softmax), fp32.
// One block = 64 q-rows of one (b,h). K tiles of 64. 256 threads, 4x4 tiles.
// mask applied BEFORE 1/sqrt(E) scaling, per reference.
// ---------------------------------------------------------------------------
__global__ __launch_bounds__(256) void attn_kernel(const int* __restrict__ mask)
{
    __shared__ float Qt[64 * 64];   // [d][q]
    __shared__ float KPt[64 * 64];  // K tile [d][k], reused as P^T [k][q]
    __shared__ float Vs[64 * 64];   // V tile [k][d]

    const int tid = threadIdx.x;
    const int q0  = blockIdx.x * 64;
    const int h   = blockIdx.y;
    const int b   = blockIdx.z;
    const int ty  = tid >> 4, tx = tid & 15;
    const int r0  = ty * 4, c0 = tx * 4;

    // Load Q tile transposed
    #pragma unroll
    for (int i = 0; i < 4; i++) {
        int idx = tid + i * 256;
        int q = idx >> 4, d4 = (idx & 15) * 4;
        float4 v = *(const float4*)&g_Q[((size_t)(b * L_ + q0 + q)) * E_ + h * 64 + d4];
        Qt[(d4 + 0) * 64 + q] = v.x;
        Qt[(d4 + 1) * 64 + q] = v.y;
        Qt[(d4 + 2) * 64 + q] = v.z;
        Qt[(d4 + 3) * 64 + q] = v.w;
    }

    float m[4], lsum[4], o[4][4];
    #pragma unroll
    for (int i = 0; i < 4; i++) {
        m[i] = -1e30f; lsum[i] = 0.f;
        o[i][0] = o[i][1] = o[i][2] = o[i][3] = 0.f;
    }
    const float INV = 0.03125f;  // 1/sqrt(1024) exactly

    for (int k0 = 0; k0 < L_; k0 += 64) {
        // Load K (transposed) and V (row-major) tiles
        #pragma unroll
        for (int i = 0; i < 4; i++) {
            int idx = tid + i * 256;
            int k = idx >> 4, d4 = (idx & 15) * 4;
            size_t base = ((size_t)(b * L_ + k0 + k)) * E_ + h * 64 + d4;
            float4 kv = *(const float4*)&g_K[base];
            KPt[(d4 + 0) * 64 + k] = kv.x;
            KPt[(d4 + 1) * 64 + k] = kv.y;
            KPt[(d4 + 2) * 64 + k] = kv.z;
            KPt[(d4 + 3) * 64 + k] = kv.w;
            *(float4*)&Vs[k * 64 + d4] = *(const float4*)&g_V[base];
        }
        __syncthreads();

        // S = Q K^T (64x64x64)
        float s[4][4] = {};
        #pragma unroll 8
        for (int d = 0; d < 64; d++) {
            float4 a  = *(const float4*)&Qt[d * 64 + r0];
            float4 bb = *(const float4*)&KPt[d * 64 + c0];
            s[0][0] += a.x * bb.x; s[0][1] += a.x * bb.y; s[0][2] += a.x * bb.z; s[0][3] += a.x * bb.w;
            s[1][0] += a.y * bb.x; s[1][1] += a.y * bb.y; s[1][2] += a.y * bb.z; s[1][3] += a.y * bb.w;
            s[2][0] += a.z * bb.x; s[2][1] += a.z * bb.y; s[2][2] += a.z * bb.z; s[2][3] += a.z * bb.w;
            s[3][0] += a.w * bb.x; s[3][1] += a.w * bb.y; s[3][2] += a.w * bb.z; s[3][3] += a.w * bb.w;
        }

        // mask (before scale) + scale; -1e20/32 = -3.125e18
        #pragma unroll
        for (int i = 0; i < 4; i++) {
            const int4 mv = *(const int4*)&mask[((size_t)b * L_ + q0 + r0 + i) * L_ + k0 + c0];
            s[i][0] = mv.x ? s[i][0] * INV : -3.125e18f;
            s[i][1] = mv.y ? s[i][1] * INV : -3.125e18f;
            s[i][2] = mv.z ? s[i][2] * INV : -3.125e18f;
            s[i][3] = mv.w ? s[i][3] * INV : -3.125e18f;
        }

        // online softmax per q-row (row group = 16 consecutive lanes)
        #pragma unroll
        for (int i = 0; i < 4; i++) {
            float mt = fmaxf(fmaxf(s[i][0], s[i][1]), fmaxf(s[i][2], s[i][3]));
            #pragma unroll
            for (int off = 1; off < 16; off <<= 1)
                mt = fmaxf(mt, __shfl_xor_sync(0xffffffffu, mt, off));
            float mn = fmaxf(m[i], mt);
            float p0 = __expf(s[i][0] - mn);
            float p1 = __expf(s[i][1] - mn);
            float p2 = __expf(s[i][2] - mn);
            float p3 = __expf(s[i][3] - mn);
            float rs = p0 + p1 + p2 + p3;
            #pragma unroll
            for (int off = 1; off < 16; off <<= 1)
                rs += __shfl_xor_sync(0xffffffffu, rs, off);
            float fac = __expf(m[i] - mn);
            lsum[i] = lsum[i] * fac + rs;
            m[i] = mn;
            o[i][0] *= fac; o[i][1] *= fac; o[i][2] *= fac; o[i][3] *= fac;
            s[i][0] = p0; s[i][1] = p1; s[i][2] = p2; s[i][3] = p3;
        }
        __syncthreads();   // all threads done reading K tile

        // write P^T into KPt: Pt[k][q]
        #pragma unroll
        for (int j = 0; j < 4; j++) {
            float4 pv = make_float4(s[0][j], s[1][j], s[2][j], s[3][j]);
            *(float4*)&KPt[(c0 + j) * 64 + r0] = pv;
        }
        __syncthreads();

        // O += P V (64x64x64)
        #pragma unroll 8
        for (int k = 0; k < 64; k++) {
            float4 a  = *(const float4*)&KPt[k * 64 + r0];
            float4 bb = *(const float4*)&Vs[k * 64 + c0];
            o[0][0] += a.x * bb.x; o[0][1] += a.x * bb.y; o[0][2] += a.x * bb.z; o[0][3] += a.x * bb.w;
            o[1][0] += a.y * bb.x; o[1][1] += a.y * bb.y; o[1][2] += a.y * bb.z; o[1][3] += a.y * bb.w;
            o[2][0] += a.z * bb.x; o[2][1] += a.z * bb.y; o[2][2] += a.z * bb.z; o[2][3] += a.z * bb.w;
            o[3][0] += a.w * bb.x; o[3][1] += a.w * bb.y; o[3][2] += a.w * bb.z; o[3][3] += a.w * bb.w;
        }
        __syncthreads();   // before next tile load overwrites KPt/Vs
    }

    #pragma unroll
    for (int i = 0; i < 4; i++) {
        float inv = 1.0f / lsum[i];
        float4 ov = make_float4(o[i][0] * inv, o[i][1] * inv, o[i][2] * inv, o[i][3] * inv);
        *(float4*)&g_A[((size_t)(b * L_ + q0 + r0 + i)) * E_ + h * 64 + c0] = ov;
    }
}

// ---------------------------------------------------------------------------
// Kernel 3: FC epilogue. out[n,e] = sum_f A[n,f]*Wfc[e,f] + bfc[e]
// 64x64 output tiles, K-loop over 1024 in steps of 64.
// ---------------------------------------------------------------------------
__global__ __launch_bounds__(256) void fc_kernel(
    const float* __restrict__ Wfc, const float* __restrict__ bfc,
    float* __restrict__ out)
{
    __shared__ float At[64 * 64];  // [f][n]
    __shared__ float Wt[64 * 64];  // [f][e]

    const int tid = threadIdx.x;
    const int n0 = blockIdx.x * 64;
    const int e0 = blockIdx.y * 64;
    const int ty = tid >> 4, tx = tid & 15;
    const int r0 = ty * 4, c0 = tx * 4;

    float acc[4][4] = {};

    for (int f0 = 0; f0 < E_; f0 += 64) {
        #pragma unroll
        for (int i = 0; i < 4; i++) {
            int idx = tid + i * 256;
            int r = idx >> 4, f4 = (idx & 15) * 4;
            float4 av = *(const float4*)&g_A[(size_t)(n0 + r) * E_ + f0 + f4];
            At[(f4 + 0) * 64 + r] = av.x;
            At[(f4 + 1) * 64 + r] = av.y;
            At[(f4 + 2) * 64 + r] = av.z;
            At[(f4 + 3) * 64 + r] = av.w;
            float4 wv = *(const float4*)&Wfc[(size_t)(e0 + r) * E_ + f0 + f4];
            Wt[(f4 + 0) * 64 + r] = wv.x;
            Wt[(f4 + 1) * 64 + r] = wv.y;
            Wt[(f4 + 2) * 64 + r] = wv.z;
            Wt[(f4 + 3) * 64 + r] = wv.w;
        }
        __syncthreads();

        #pragma unroll 8
        for (int f = 0; f < 64; f++) {
            float4 a = *(const float4*)&At[f * 64 + r0];
            float4 w = *(const float4*)&Wt[f * 64 + c0];
            acc[0][0] += a.x * w.x; acc[0][1] += a.x * w.y; acc[0][2] += a.x * w.z; acc[0][3] += a.x * w.w;
            acc[1][0] += a.y * w.x; acc[1][1] += a.y * w.y; acc[1][2] += a.y * w.z; acc[1][3] += a.y * w.w;
            acc[2][0] += a.z * w.x; acc[2][1] += a.z * w.y; acc[2][2] += a.z * w.z; acc[2][3] += a.z * w.w;
            acc[3][0] += a.w * w.x; acc[3][1] += a.w * w.y; acc[3][2] += a.w * w.z; acc[3][3] += a.w * w.w;
        }
        __syncthreads();
    }

    const float4 bias = *(const float4*)&bfc[e0 + c0];
    #pragma unroll
    for (int i = 0; i < 4; i++) {
        float4 ov = make_float4(acc[i][0] + bias.x, acc[i][1] + bias.y,
                                acc[i][2] + bias.z, acc[i][3] + bias.w);
        *(float4*)&out[(size_t)(n0 + r0 + i) * E_ + e0 + c0] = ov;
    }
}

// ---------------------------------------------------------------------------
// Launch.  Input order (metadata): query, value, key, mask, Wq, Wk, Wv, Wfc, bfc
// ---------------------------------------------------------------------------
extern "C" void kernel_launch(void* const* d_in, const int* in_sizes, int n_in,
                              void* d_out, int out_size)
{
    const float* query = (const float*)d_in[0];
    const float* value = (const float*)d_in[1];
    const float* key   = (const float*)d_in[2];
    const int*   mask  = (const int*)d_in[3];
    const float* Wq    = (const float*)d_in[4];
    const float* Wk    = (const float*)d_in[5];
    const float* Wv    = (const float*)d_in[6];
    const float* Wfc   = (const float*)d_in[7];
    const float* bfc   = (const float*)d_in[8];
    float* out = (float*)d_out;

    proj_kernel<<<dim3(L_ / 64, H_, 3 * B_), 256>>>(query, key, value, Wq, Wk, Wv);
    attn_kernel<<<dim3(L_ / 64, H_, B_), 256>>>(mask);
    fc_kernel<<<dim3((B_ * L_) / 64, E_ / 64), 256>>>(Wfc, bfc, out);
}